// round 16
// baseline (speedup 1.0000x reference)
#include <cuda_runtime.h>
#include <cuda_fp16.h>
#include <cstdint>

// Problem constants
constexpr int Bsz = 4;
constexpr int Sq  = 2048;
constexpr int Dm  = 1024;

// Scratch (device globals; no allocation allowed).
// "blocked" fp16 layout: matrix [R x K] split into 16x16 blocks, block
// (br,bk) stored at (br*(K/16)+bk)*256 halves; inside a block, 16B chunk
// (g,q), g=0..7,q=0..3 (chunk idx = g*4+q), holds halves
//   x: [row g,   k 2q,2q+1]   y: [row g,   k 2q+8,2q+9]
//   z: [row g+8, k 2q,2q+1]   w: [row g+8, k 2q+8,2q+9]
// One LDS.128 = one full m16n8k16 A-fragment (regs x,z,y,w) or two
// B-fragments (n=g via x,y and n=g+8 via z,w).
__device__ __half g_Xh  [(long)Bsz * Sq * Dm];
__device__ __half g_Wcat[(long)3 * Dm * Dm];    // WqT | WkT | WvT (row-concat)
__device__ __half g_Qh  [(long)Bsz * Sq * Dm];
__device__ __half g_Kh  [(long)Bsz * Sq * Dm];
__device__ __half g_Vt  [(long)Bsz * Sq * Dm];  // V^T per batch, blocked
__device__ __half g_Ph  [(long)Bsz * Sq * Sq];  // E = exp(s/32) masked, blocked
__device__ float  g_Psum[(long)Bsz * Sq * 16];  // per-row partial sums (16 n-slots)
__device__ float  g_Inv [(long)Bsz * Sq];       // 1 / row sum

// ---------------------------------------------------------------------------
// helpers
// ---------------------------------------------------------------------------
__device__ __forceinline__ void cp16(void* s, const void* g) {
    uint32_t sa = (uint32_t)__cvta_generic_to_shared(s);
    asm volatile("cp.async.cg.shared.global [%0], [%1], 16;\n" :: "r"(sa), "l"(g));
}

__device__ __forceinline__ void mma_f16(float* d,
    uint32_t a0, uint32_t a1, uint32_t a2, uint32_t a3,
    uint32_t b0, uint32_t b1) {
    asm volatile(
        "mma.sync.aligned.m16n8k16.row.col.f32.f16.f16.f32 "
        "{%0,%1,%2,%3},{%4,%5,%6,%7},{%8,%9},{%0,%1,%2,%3};"
        : "+f"(d[0]), "+f"(d[1]), "+f"(d[2]), "+f"(d[3])
        : "r"(a0), "r"(a1), "r"(a2), "r"(a3), "r"(b0), "r"(b1));
}

// f16-accumulator variant (2x rate on legacy pipe); D = 2 x f16x2 regs
__device__ __forceinline__ void mma_f16h(uint32_t* d,
    uint32_t a0, uint32_t a1, uint32_t a2, uint32_t a3,
    uint32_t b0, uint32_t b1) {
    asm volatile(
        "mma.sync.aligned.m16n8k16.row.col.f16.f16.f16.f16 "
        "{%0,%1},{%2,%3,%4,%5},{%6,%7},{%0,%1};"
        : "+r"(d[0]), "+r"(d[1])
        : "r"(a0), "r"(a1), "r"(a2), "r"(a3), "r"(b0), "r"(b1));
}

__device__ __forceinline__ uint32_t pack2(float a, float b) {
    __half2 h = __floats2half2_rn(a, b);
    return *(uint32_t*)&h;
}

// half offset of element (r, k) inside blocked [R x K] matrix (Kd = K size).
__device__ __forceinline__ long blk_off(int r, int k, int Kd) {
    return ((long)(r >> 4) * (Kd >> 4) + (k >> 4)) * 256
         + ((r & 7) * 4 + ((k >> 1) & 3)) * 8
         + ((r >> 3) & 1) * 4 + ((k >> 3) & 1) * 2 + (k & 1);
}

// ---------------------------------------------------------------------------
// Pack fp32 row-major [R x Kd] -> fp16 blocked.  One thread produces TWO
// adjacent 16B chunks from 4 coalesced float4 loads.  nth = R*Kd/16.
// ---------------------------------------------------------------------------
__global__ void __launch_bounds__(256)
pack_rm(const float* __restrict__ in, __half* __restrict__ out,
        int Kd, long nth)
{
    long t = (long)blockIdx.x * blockDim.x + threadIdx.x;
    if (t >= nth) return;
    const long blk = t >> 4;
    const int sub = (int)(t & 15);
    const int g = sub >> 1, qh = sub & 1;
    const int Kb = Kd >> 4;
    const int rb = (int)(blk / Kb), kb = (int)(blk % Kb);
    const int r = rb * 16 + g;
    const float* p = in + (long)r * Kd + kb * 16 + qh * 4;
    float4 lo  = *(const float4*)p;
    float4 lo8 = *(const float4*)(p + 8);
    float4 hi  = *(const float4*)(p + (long)8 * Kd);
    float4 hi8 = *(const float4*)(p + (long)8 * Kd + 8);
    uint4 u0, u1;
    u0.x = pack2(lo.x, lo.y);   u0.y = pack2(lo8.x, lo8.y);
    u0.z = pack2(hi.x, hi.y);   u0.w = pack2(hi8.x, hi8.y);
    u1.x = pack2(lo.z, lo.w);   u1.y = pack2(lo8.z, lo8.w);
    u1.z = pack2(hi.z, hi.w);   u1.w = pack2(hi8.z, hi8.w);
    uint4* o = (uint4*)out + blk * 32 + g * 4 + 2 * qh;
    o[0] = u0;
    o[1] = u1;
}

// ---------------------------------------------------------------------------
// Transpose 3 fp32 [Dm x Dm] weights -> fp16 blocked [Dm x Dm] each, into
// one concatenated buffer.  blockIdx.z selects the source.
// ---------------------------------------------------------------------------
__global__ void __launch_bounds__(256)
pack_t3(const float* __restrict__ w0, const float* __restrict__ w1,
        const float* __restrict__ w2, __half* __restrict__ out)
{
    __shared__ float t[32][33];
    const float* in = (blockIdx.z == 0) ? w0 : (blockIdx.z == 1) ? w1 : w2;
    __half* o = out + (long)blockIdx.z * Dm * Dm;
    const int r0 = blockIdx.x * 32, c0 = blockIdx.y * 32;
    const int x = threadIdx.x, y = threadIdx.y;     // (32, 8)
    #pragma unroll
    for (int i = 0; i < 32; i += 8)
        t[y + i][x] = in[(long)(r0 + y + i) * Dm + c0 + x];
    __syncthreads();

    const int tid = y * 32 + x;
    if (tid < 128) {
        const int blk = tid >> 5, idx = tid & 31;
        const int brl = blk >> 1, bkl = blk & 1;
        const int g = idx >> 2, q = idx & 3;
        const int E  = 16 * brl + g;       // out-row within 32 (orig col)
        const int S0 = 16 * bkl + 2 * q;   // out-k within 32 (orig row)
        uint4 u;
        u.x = pack2(t[S0][E],         t[S0 + 1][E]);
        u.y = pack2(t[S0 + 8][E],     t[S0 + 9][E]);
        u.z = pack2(t[S0][E + 8],     t[S0 + 1][E + 8]);
        u.w = pack2(t[S0 + 8][E + 8], t[S0 + 9][E + 8]);
        const long chunk =
            ((long)((c0 >> 4) + brl) * (Dm >> 4) + (r0 >> 4) + bkl) * 32 + idx;
        ((uint4*)o)[chunk] = u;
    }
}

// ---------------------------------------------------------------------------
// Row-sum finisher: Inv[row] = 1 / sum of that row's partial sums.
// ---------------------------------------------------------------------------
__global__ void __launch_bounds__(256)
rowsum_k()
{
    const int row = blockIdx.x * 256 + threadIdx.x;    // 0 .. Bsz*Sq-1
    const int i = row & (Sq - 1);
    const int nbmax = ((i & ~63) + 63) >> 7;
    const float* p = g_Psum + (long)row * 16;
    float s = 0.f;
    for (int nb = 0; nb <= nbmax; nb++) s += p[nb];
    g_Inv[row] = 1.0f / s;
}

// ---------------------------------------------------------------------------
// FP16 mma.sync GEMM on blocked operands:  C[M,N] = A[M,K] * B[N,K]^T
// CTA 64(M) x 128(N), 4 warps (2x2), warp tile 32x64.
// K-chunk 32 per stage, 4 stages, ONE __syncthreads per chunk.
// HACC: accumulate in f16 over K=128 spans (4 iters), flush into fp32
//       (2x HMMA rate on the legacy pipe; span-bounded rounding noise).
// REVY: reverse blockIdx.y -> m0 so heaviest CTAs launch first.
// EPI: 3 = fused QKV routing (Q/K blocked, V transposed blocked per batch)
//      5 = scores: mask + exp(s/32) -> blocked fp16 E into g_Ph (batched),
//          plus per-row partial sums into g_Psum
//      6 = PV: fp32 row-major scaled by g_Inv[row]
// ---------------------------------------------------------------------------
template <bool CAUSAL_SKIP, bool KLIMIT, bool REVY, int EPI, bool HACC>
__global__ void __launch_bounds__(128, 3)
hgemm(const __half* __restrict__ A, const __half* __restrict__ B, void* Cout,
      int Kd, int ldc, long sA, long sB, long sC)
{
    const int by = REVY ? (gridDim.y - 1 - blockIdx.y) : blockIdx.y;
    const int m0 = by * 64;
    const int n0 = blockIdx.x * 128;
    if (CAUSAL_SKIP && n0 > m0 + 63) return;

    A += (long)blockIdx.z * sA;
    B += (long)blockIdx.z * sB;

    const int Keff = KLIMIT ? min(Kd, m0 + 64) : Kd;
    const int nkt  = Keff >> 5;          // K-chunks of 32
    const int Kb   = Kd >> 4;            // 16-K blocks per row

    __shared__ uint4 sm[4][768];         // 48 KB

    const int tid  = threadIdx.x;
    const int warp = tid >> 5;           // 0..3
    const int lane = tid & 31;
    const int wm   = warp >> 1;          // 0..1 (32 M-rows)
    const int wn   = warp & 1;           // 0..1 (64 N-cols)

    // A loader: 256 chunks per stage, 2/thread
    const uint4* agp[2];  int asmi[2];
    #pragma unroll
    for (int i = 0; i < 2; i++) {
        const int c  = tid + i * 128;
        const int kb = c >> 7, mb = (c >> 5) & 3, ln = c & 31;
        agp[i]  = (const uint4*)A + ((long)((m0 >> 4) + mb) * Kb + kb) * 32 + ln;
        asmi[i] = kb * 128 + mb * 32 + ln;
    }
    // B loader: 512 chunks per stage, 4/thread
    const uint4* bgp[4];  int bsmi[4];
    #pragma unroll
    for (int i = 0; i < 4; i++) {
        const int c  = tid + i * 128;
        const int kb = c >> 8, nb = (c >> 5) & 7, ln = c & 31;
        bgp[i]  = (const uint4*)B + ((long)((n0 >> 4) + nb) * Kb + kb) * 32 + ln;
        bsmi[i] = 256 + kb * 256 + nb * 32 + ln;
    }

    auto load_stage = [&](int st, int kt) {
        const long koff = (long)kt * 64;
        #pragma unroll
        for (int i = 0; i < 2; i++) cp16(&sm[st][asmi[i]], agp[i] + koff);
        #pragma unroll
        for (int i = 0; i < 4; i++) cp16(&sm[st][bsmi[i]], bgp[i] + koff);
    };

    #pragma unroll
    for (int s = 0; s < 3; s++) {
        if (s < nkt) load_stage(s, s);
        asm volatile("cp.async.commit_group;\n");
    }

    float acc[2][8][4] = {};
    uint32_t hacc[2][8][2] = {};

    for (int kt = 0; kt < nkt; ++kt) {
        const int cur = kt & 3;
        asm volatile("cp.async.wait_group 2;\n");
        __syncthreads();   // data ready + all warps done reading slot (kt+3)&3

        if (kt + 3 < nkt) load_stage((kt + 3) & 3, kt + 3);
        asm volatile("cp.async.commit_group;\n");

        #pragma unroll
        for (int kb = 0; kb < 2; kb++) {
            uint4 Aq[2], Bq[4];
            #pragma unroll
            for (int mi = 0; mi < 2; mi++)
                Aq[mi] = sm[cur][kb * 128 + (wm * 2 + mi) * 32 + lane];
            #pragma unroll
            for (int nj = 0; nj < 4; nj++)
                Bq[nj] = sm[cur][256 + kb * 256 + (wn * 4 + nj) * 32 + lane];

            #pragma unroll
            for (int mi = 0; mi < 2; mi++)
                #pragma unroll
                for (int nj = 0; nj < 4; nj++) {
                    if (HACC) {
                        mma_f16h(hacc[mi][nj * 2],     Aq[mi].x, Aq[mi].z, Aq[mi].y, Aq[mi].w,
                                 Bq[nj].x, Bq[nj].y);
                        mma_f16h(hacc[mi][nj * 2 + 1], Aq[mi].x, Aq[mi].z, Aq[mi].y, Aq[mi].w,
                                 Bq[nj].z, Bq[nj].w);
                    } else {
                        mma_f16(acc[mi][nj * 2],     Aq[mi].x, Aq[mi].z, Aq[mi].y, Aq[mi].w,
                                Bq[nj].x, Bq[nj].y);
                        mma_f16(acc[mi][nj * 2 + 1], Aq[mi].x, Aq[mi].z, Aq[mi].y, Aq[mi].w,
                                Bq[nj].z, Bq[nj].w);
                    }
                }
        }

        // flush f16 span accumulators into fp32 every 4 K-chunks (K=128)
        if (HACC && ((kt & 3) == 3 || kt == nkt - 1)) {
            #pragma unroll
            for (int mi = 0; mi < 2; mi++)
                #pragma unroll
                for (int nt = 0; nt < 8; nt++) {
                    const float2 lo = __half22float2(*(__half2*)&hacc[mi][nt][0]);
                    const float2 hi = __half22float2(*(__half2*)&hacc[mi][nt][1]);
                    acc[mi][nt][0] += lo.x;  acc[mi][nt][1] += lo.y;
                    acc[mi][nt][2] += hi.x;  acc[mi][nt][3] += hi.y;
                    hacc[mi][nt][0] = 0u;    hacc[mi][nt][1] = 0u;
                }
        }
    }

    // Epilogue
    if (EPI == 3) {
        // fused QKV: route by output column group (uniform per CTA)
        const int w  = n0 >> 10;            // 0=Q, 1=K, 2=V
        const int nb = n0 & 1023;           // column base within the target
        #pragma unroll
        for (int mi = 0; mi < 2; mi++) {
            #pragma unroll
            for (int nt = 0; nt < 8; nt++) {
                const int r0 = m0 + wm * 32 + mi * 16 + (lane >> 2);
                const int c0 = nb + wn * 64 + nt * 8 + 2 * (lane & 3);
                if (w == 0) {
                    const long off = blk_off(r0, c0, Dm);
                    *(uint32_t*)(g_Qh + off)     = pack2(acc[mi][nt][0], acc[mi][nt][1]);
                    *(uint32_t*)(g_Qh + off + 4) = pack2(acc[mi][nt][2], acc[mi][nt][3]);
                } else if (w == 1) {
                    const long off = blk_off(r0, c0, Dm);
                    *(uint32_t*)(g_Kh + off)     = pack2(acc[mi][nt][0], acc[mi][nt][1]);
                    *(uint32_t*)(g_Kh + off + 4) = pack2(acc[mi][nt][2], acc[mi][nt][3]);
                } else {
                    const int b   = r0 >> 11;
                    const int rb0 = r0 & 2047;
                    __half* Vb = g_Vt + (long)b * Sq * Dm;
                    Vb[blk_off(c0,     rb0,     Sq)] = __float2half_rn(acc[mi][nt][0]);
                    Vb[blk_off(c0 + 1, rb0,     Sq)] = __float2half_rn(acc[mi][nt][1]);
                    Vb[blk_off(c0,     rb0 + 8, Sq)] = __float2half_rn(acc[mi][nt][2]);
                    Vb[blk_off(c0 + 1, rb0 + 8, Sq)] = __float2half_rn(acc[mi][nt][3]);
                }
            }
        }
    } else if (EPI == 5) {
        // scores: causal mask, E = exp(s/32) (fp32), blocked store, row sums
        __half* Eb = g_Ph + (long)blockIdx.z * Sq * Sq;
        const int lg = lane >> 2, q = lane & 3;
        float rs[2][2] = {{0.f, 0.f}, {0.f, 0.f}};
        #pragma unroll
        for (int mi = 0; mi < 2; mi++) {
            const int ra = m0 + wm * 32 + mi * 16 + lg;
            #pragma unroll
            for (int nt = 0; nt < 8; nt++) {
                const int c0 = n0 + wn * 64 + nt * 8 + 2 * q;
                const float e00 = (c0     <= ra    ) ? __expf(acc[mi][nt][0] * 0.03125f) : 0.f;
                const float e01 = (c0 + 1 <= ra    ) ? __expf(acc[mi][nt][1] * 0.03125f) : 0.f;
                const float e10 = (c0     <= ra + 8) ? __expf(acc[mi][nt][2] * 0.03125f) : 0.f;
                const float e11 = (c0 + 1 <= ra + 8) ? __expf(acc[mi][nt][3] * 0.03125f) : 0.f;
                *(uint32_t*)(Eb + blk_off(ra,     c0, Sq)) = pack2(e00, e01);
                *(uint32_t*)(Eb + blk_off(ra + 8, c0, Sq)) = pack2(e10, e11);
                rs[mi][0] += e00 + e01;
                rs[mi][1] += e10 + e11;
            }
        }
        #pragma unroll
        for (int mi = 0; mi < 2; mi++)
            #pragma unroll
            for (int hi = 0; hi < 2; hi++) {
                rs[mi][hi] += __shfl_xor_sync(0xFFFFFFFFu, rs[mi][hi], 1);
                rs[mi][hi] += __shfl_xor_sync(0xFFFFFFFFu, rs[mi][hi], 2);
            }
        __syncthreads();                     // mainloop smem reads all done
        float* ps = (float*)&sm[0][0];       // reuse stage-0 smem
        if (q == 0) {
            #pragma unroll
            for (int mi = 0; mi < 2; mi++)
                #pragma unroll
                for (int hi = 0; hi < 2; hi++)
                    ps[(wm * 32 + mi * 16 + hi * 8 + lg) * 2 + wn] = rs[mi][hi];
        }
        __syncthreads();
        if (tid < 64)
            g_Psum[((long)blockIdx.z * Sq + m0 + tid) * 16 + (n0 >> 7)] =
                ps[tid * 2] + ps[tid * 2 + 1];
    } else {
        // EPI == 6: PV output, scaled by per-row inverse sum
        float* Cf = (float*)Cout + (long)blockIdx.z * sC;
        const float* Iv = g_Inv + (long)blockIdx.z * Sq;
        #pragma unroll
        for (int mi = 0; mi < 2; mi++) {
            const int r0 = m0 + wm * 32 + mi * 16 + (lane >> 2);
            const float i0 = Iv[r0], i1 = Iv[r0 + 8];
            #pragma unroll
            for (int nt = 0; nt < 8; nt++) {
                const int c0 = n0 + wn * 64 + nt * 8 + 2 * (lane & 3);
                *(float2*)&Cf[(long)r0 * ldc + c0] =
                    make_float2(acc[mi][nt][0] * i0, acc[mi][nt][1] * i0);
                *(float2*)&Cf[(long)(r0 + 8) * ldc + c0] =
                    make_float2(acc[mi][nt][2] * i1, acc[mi][nt][3] * i1);
            }
        }
    }
}

// ---------------------------------------------------------------------------
extern "C" void kernel_launch(void* const* d_in, const int* in_sizes, int n_in,
                              void* d_out, int out_size)
{
    const float* x  = (const float*)d_in[0];
    const float* Wq = (const float*)d_in[1];
    const float* Wk = (const float*)d_in[2];
    const float* Wv = (const float*)d_in[3];
    float* out = (float*)d_out;

    __half *Xh, *Wcat, *Qh, *Kh, *Vt, *Ph;
    cudaGetSymbolAddress((void**)&Xh,   g_Xh);
    cudaGetSymbolAddress((void**)&Wcat, g_Wcat);
    cudaGetSymbolAddress((void**)&Qh,   g_Qh);
    cudaGetSymbolAddress((void**)&Kh,   g_Kh);
    cudaGetSymbolAddress((void**)&Vt,   g_Vt);
    cudaGetSymbolAddress((void**)&Ph,   g_Ph);

    // Max shared-memory carveout so 3 CTAs x 48KB fit per SM
    cudaFuncSetAttribute((const void*)hgemm<false, false, false, 3, true>,
        cudaFuncAttributePreferredSharedMemoryCarveout, 100);
    cudaFuncSetAttribute((const void*)hgemm<true, false, true, 5, true>,
        cudaFuncAttributePreferredSharedMemoryCarveout, 100);
    cudaFuncSetAttribute((const void*)hgemm<false, true, true, 6, false>,
        cudaFuncAttributePreferredSharedMemoryCarveout, 100);

    const int M = Bsz * Sq;   // 8192

    // 0) pack x; pack all three W^T in ONE launch
    {
        const long nth = (long)M * Dm / 16;
        pack_rm<<<(int)((nth + 255) / 256), 256>>>(x, Xh, Dm, nth);
        dim3 tb(32, 8);
        dim3 gw(Dm / 32, Dm / 32, 3);
        pack_t3<<<gw, tb>>>(Wq, Wk, Wv, Wcat);
    }

    // 1) Fused QKV projection (f16 span-accumulate)
    {
        dim3 grid((3 * Dm) / 128, M / 64, 1);
        hgemm<false, false, false, 3, true><<<grid, 128>>>(
            Xh, Wcat, nullptr, Dm, Dm, 0, 0, 0);
    }

    // 2) Scores + mask + exp + partial row sums (f16 span-accumulate)
    {
        dim3 grid(Sq / 128, Sq / 64, Bsz);
        hgemm<true, false, true, 5, true><<<grid, 128>>>(
            Qh, Kh, nullptr, Dm, Sq,
            (long)Sq * Dm, (long)Sq * Dm, 0);
    }

    // 3) Row-sum finisher -> Inv
    rowsum_k<<<(Bsz * Sq) / 256, 256>>>();

    // 4) O = (E Vt^T) * Inv (f32 accumulate; causal K-limit, heavy first)
    {
        dim3 grid(Dm / 128, Sq / 64, Bsz);
        hgemm<false, true, true, 6, false><<<grid, 128>>>(
            Ph, Vt, out, Sq, Dm,
            (long)Sq * Sq, (long)Sq * Dm, (long)Sq * Dm);
    }

    (void)in_sizes; (void)n_in; (void)out_size;
}

// round 17
// speedup vs baseline: 1.0349x; 1.0349x over previous
#include <cuda_runtime.h>
#include <cuda_fp16.h>
#include <cstdint>

// Problem constants
constexpr int Bsz = 4;
constexpr int Sq  = 2048;
constexpr int Dm  = 1024;

// Scratch (device globals; no allocation allowed).
// "blocked" fp16 layout: matrix [R x K] split into 16x16 blocks, block
// (br,bk) stored at (br*(K/16)+bk)*256 halves; inside a block, 16B chunk
// (g,q), g=0..7,q=0..3 (chunk idx = g*4+q), holds halves
//   x: [row g,   k 2q,2q+1]   y: [row g,   k 2q+8,2q+9]
//   z: [row g+8, k 2q,2q+1]   w: [row g+8, k 2q+8,2q+9]
// One LDS.128 = one full m16n8k16 A-fragment (regs x,z,y,w) or two
// B-fragments (n=g via x,y and n=g+8 via z,w).
__device__ __half g_Xh  [(long)Bsz * Sq * Dm];
__device__ __half g_Wcat[(long)3 * Dm * Dm];    // WqT | WkT | WvT (row-concat)
__device__ __half g_Qh  [(long)Bsz * Sq * Dm];
__device__ __half g_Kh  [(long)Bsz * Sq * Dm];
__device__ __half g_Vt  [(long)Bsz * Sq * Dm];  // V^T per batch, blocked
__device__ __half g_Ph  [(long)Bsz * Sq * Sq];  // E = exp(s/32) masked, blocked
__device__ float  g_Psum[(long)Bsz * Sq * 16];  // per-row partial sums (16 n-slots)
__device__ float  g_Inv [(long)Bsz * Sq];       // 1 / row sum

// ---------------------------------------------------------------------------
// helpers
// ---------------------------------------------------------------------------
__device__ __forceinline__ void cp16(void* s, const void* g) {
    uint32_t sa = (uint32_t)__cvta_generic_to_shared(s);
    asm volatile("cp.async.cg.shared.global [%0], [%1], 16;\n" :: "r"(sa), "l"(g));
}

__device__ __forceinline__ void mma_f16(float* d,
    uint32_t a0, uint32_t a1, uint32_t a2, uint32_t a3,
    uint32_t b0, uint32_t b1) {
    asm volatile(
        "mma.sync.aligned.m16n8k16.row.col.f32.f16.f16.f32 "
        "{%0,%1,%2,%3},{%4,%5,%6,%7},{%8,%9},{%0,%1,%2,%3};"
        : "+f"(d[0]), "+f"(d[1]), "+f"(d[2]), "+f"(d[3])
        : "r"(a0), "r"(a1), "r"(a2), "r"(a3), "r"(b0), "r"(b1));
}

__device__ __forceinline__ uint32_t pack2(float a, float b) {
    __half2 h = __floats2half2_rn(a, b);
    return *(uint32_t*)&h;
}

// half offset of element (r, k) inside blocked [R x K] matrix (Kd = K size).
__device__ __forceinline__ long blk_off(int r, int k, int Kd) {
    return ((long)(r >> 4) * (Kd >> 4) + (k >> 4)) * 256
         + ((r & 7) * 4 + ((k >> 1) & 3)) * 8
         + ((r >> 3) & 1) * 4 + ((k >> 3) & 1) * 2 + (k & 1);
}

// ---------------------------------------------------------------------------
// Pack fp32 row-major [R x Kd] -> fp16 blocked.  One thread produces TWO
// adjacent 16B chunks from 4 coalesced float4 loads.  nth = R*Kd/16.
// ---------------------------------------------------------------------------
__global__ void __launch_bounds__(256)
pack_rm(const float* __restrict__ in, __half* __restrict__ out,
        int Kd, long nth)
{
    long t = (long)blockIdx.x * blockDim.x + threadIdx.x;
    if (t >= nth) return;
    const long blk = t >> 4;
    const int sub = (int)(t & 15);
    const int g = sub >> 1, qh = sub & 1;
    const int Kb = Kd >> 4;
    const int rb = (int)(blk / Kb), kb = (int)(blk % Kb);
    const int r = rb * 16 + g;
    const float* p = in + (long)r * Kd + kb * 16 + qh * 4;
    float4 lo  = *(const float4*)p;
    float4 lo8 = *(const float4*)(p + 8);
    float4 hi  = *(const float4*)(p + (long)8 * Kd);
    float4 hi8 = *(const float4*)(p + (long)8 * Kd + 8);
    uint4 u0, u1;
    u0.x = pack2(lo.x, lo.y);   u0.y = pack2(lo8.x, lo8.y);
    u0.z = pack2(hi.x, hi.y);   u0.w = pack2(hi8.x, hi8.y);
    u1.x = pack2(lo.z, lo.w);   u1.y = pack2(lo8.z, lo8.w);
    u1.z = pack2(hi.z, hi.w);   u1.w = pack2(hi8.z, hi8.w);
    uint4* o = (uint4*)out + blk * 32 + g * 4 + 2 * qh;
    o[0] = u0;
    o[1] = u1;
}

// ---------------------------------------------------------------------------
// Transpose 3 fp32 [Dm x Dm] weights -> fp16 blocked [Dm x Dm] each, into
// one concatenated buffer.  blockIdx.z selects the source.
// ---------------------------------------------------------------------------
__global__ void __launch_bounds__(256)
pack_t3(const float* __restrict__ w0, const float* __restrict__ w1,
        const float* __restrict__ w2, __half* __restrict__ out)
{
    __shared__ float t[32][33];
    const float* in = (blockIdx.z == 0) ? w0 : (blockIdx.z == 1) ? w1 : w2;
    __half* o = out + (long)blockIdx.z * Dm * Dm;
    const int r0 = blockIdx.x * 32, c0 = blockIdx.y * 32;
    const int x = threadIdx.x, y = threadIdx.y;     // (32, 8)
    #pragma unroll
    for (int i = 0; i < 32; i += 8)
        t[y + i][x] = in[(long)(r0 + y + i) * Dm + c0 + x];
    __syncthreads();

    const int tid = y * 32 + x;
    if (tid < 128) {
        const int blk = tid >> 5, idx = tid & 31;
        const int brl = blk >> 1, bkl = blk & 1;
        const int g = idx >> 2, q = idx & 3;
        const int E  = 16 * brl + g;       // out-row within 32 (orig col)
        const int S0 = 16 * bkl + 2 * q;   // out-k within 32 (orig row)
        uint4 u;
        u.x = pack2(t[S0][E],         t[S0 + 1][E]);
        u.y = pack2(t[S0 + 8][E],     t[S0 + 9][E]);
        u.z = pack2(t[S0][E + 8],     t[S0 + 1][E + 8]);
        u.w = pack2(t[S0 + 8][E + 8], t[S0 + 9][E + 8]);
        const long chunk =
            ((long)((c0 >> 4) + brl) * (Dm >> 4) + (r0 >> 4) + bkl) * 32 + idx;
        ((uint4*)o)[chunk] = u;
    }
}

// ---------------------------------------------------------------------------
// Row-sum finisher: Inv[row] = 1 / sum of that row's partial sums.
// ---------------------------------------------------------------------------
__global__ void __launch_bounds__(256)
rowsum_k()
{
    const int row = blockIdx.x * 256 + threadIdx.x;    // 0 .. Bsz*Sq-1
    const int i = row & (Sq - 1);
    const int nbmax = ((i & ~63) + 63) >> 7;
    const float* p = g_Psum + (long)row * 16;
    float s = 0.f;
    for (int nb = 0; nb <= nbmax; nb++) s += p[nb];
    g_Inv[row] = 1.0f / s;
}

// ---------------------------------------------------------------------------
// FP16 mma.sync GEMM on blocked operands:  C[M,N] = A[M,K] * B[N,K]^T
// CTA 64(M) x 128(N), 4 warps (2x2), warp tile 32x64.
// K-chunk 64 per pipeline stage (four 16-K blocks), 3 stages (72 KB dynamic
// smem), ONE __syncthreads per K64.  f32 accumulation throughout.
// Diagonal warp skip: in causal scores, a warp whose whole 64-col span is
// above the diagonal skips its MMAs.
// REVY: reverse blockIdx.y -> m0 so heaviest CTAs launch first.
// EPI: 3 = fused QKV routing (Q/K blocked, V transposed blocked per batch)
//      5 = scores: mask + exp(s/32) -> blocked fp16 E into g_Ph (batched),
//          plus per-row partial sums into g_Psum
//      6 = PV: fp32 row-major scaled by g_Inv[row]
// ---------------------------------------------------------------------------
template <bool CAUSAL_SKIP, bool KLIMIT, bool REVY, int EPI>
__global__ void __launch_bounds__(128, 3)
hgemm(const __half* __restrict__ A, const __half* __restrict__ B, void* Cout,
      int Kd, int ldc, long sA, long sB, long sC)
{
    const int by = REVY ? (gridDim.y - 1 - blockIdx.y) : blockIdx.y;
    const int m0 = by * 64;
    const int n0 = blockIdx.x * 128;
    if (CAUSAL_SKIP && n0 > m0 + 63) return;

    A += (long)blockIdx.z * sA;
    B += (long)blockIdx.z * sB;

    const int Keff = KLIMIT ? min(Kd, m0 + 64) : Kd;
    const int nkt  = Keff >> 6;          // K-chunks of 64
    const int Kb   = Kd >> 4;            // 16-K blocks per row

    // dynamic smem: 3 stages x 1536 chunks (A 512 @ [0,512), B 1024 @ [512,1536))
    extern __shared__ uint4 smd[];

    const int tid  = threadIdx.x;
    const int warp = tid >> 5;           // 0..3
    const int lane = tid & 31;
    const int wm   = warp >> 1;          // 0..1 (32 M-rows)
    const int wn   = warp & 1;           // 0..1 (64 N-cols)

    // causal diagonal warp skip (scores only): warp's columns all masked
    const bool wskip = CAUSAL_SKIP && (n0 + wn * 64 > m0 + 63);

    // A loader: 512 chunks per stage, 4/thread
    const uint4* agp[4];  int asmi[4];
    #pragma unroll
    for (int i = 0; i < 4; i++) {
        const int c  = tid + i * 128;
        const int kb = c >> 7, mb = (c >> 5) & 3, ln = c & 31;
        agp[i]  = (const uint4*)A + ((long)((m0 >> 4) + mb) * Kb + kb) * 32 + ln;
        asmi[i] = kb * 128 + mb * 32 + ln;
    }
    // B loader: 1024 chunks per stage, 8/thread
    const uint4* bgp[8];  int bsmi[8];
    #pragma unroll
    for (int i = 0; i < 8; i++) {
        const int c  = tid + i * 128;
        const int kb = c >> 8, nb = (c >> 5) & 7, ln = c & 31;
        bgp[i]  = (const uint4*)B + ((long)((n0 >> 4) + nb) * Kb + kb) * 32 + ln;
        bsmi[i] = 512 + kb * 256 + nb * 32 + ln;
    }

    auto load_stage = [&](int st, int kt) {
        const long koff = (long)kt * 128;   // 4 blocks of 32 chunks per K64
        uint4* s = smd + st * 1536;
        #pragma unroll
        for (int i = 0; i < 4; i++) cp16(&s[asmi[i]], agp[i] + koff);
        #pragma unroll
        for (int i = 0; i < 8; i++) cp16(&s[bsmi[i]], bgp[i] + koff);
    };

    #pragma unroll
    for (int s = 0; s < 2; s++) {
        if (s < nkt) load_stage(s, s);
        asm volatile("cp.async.commit_group;\n");
    }

    float acc[2][8][4] = {};

    int cur = 0;
    for (int kt = 0; kt < nkt; ++kt) {
        asm volatile("cp.async.wait_group 1;\n");
        __syncthreads();   // data ready + all warps done reading recycled slot

        if (kt + 2 < nkt) {
            int nxt = cur - 1; if (nxt < 0) nxt = 2;   // (cur+2) mod 3
            load_stage(nxt, kt + 2);
        }
        asm volatile("cp.async.commit_group;\n");

        const uint4* s = smd + cur * 1536;
        if (!wskip) {
            #pragma unroll
            for (int kb = 0; kb < 4; kb++) {
                uint4 Aq[2], Bq[4];
                #pragma unroll
                for (int mi = 0; mi < 2; mi++)
                    Aq[mi] = s[kb * 128 + (wm * 2 + mi) * 32 + lane];
                #pragma unroll
                for (int nj = 0; nj < 4; nj++)
                    Bq[nj] = s[512 + kb * 256 + (wn * 4 + nj) * 32 + lane];

                #pragma unroll
                for (int mi = 0; mi < 2; mi++)
                    #pragma unroll
                    for (int nj = 0; nj < 4; nj++) {
                        mma_f16(acc[mi][nj * 2],     Aq[mi].x, Aq[mi].z, Aq[mi].y, Aq[mi].w,
                                Bq[nj].x, Bq[nj].y);
                        mma_f16(acc[mi][nj * 2 + 1], Aq[mi].x, Aq[mi].z, Aq[mi].y, Aq[mi].w,
                                Bq[nj].z, Bq[nj].w);
                    }
            }
        }
        cur = (cur == 2) ? 0 : cur + 1;
    }

    // Epilogue
    if (EPI == 3) {
        // fused QKV: route by output column group (uniform per CTA)
        const int w  = n0 >> 10;            // 0=Q, 1=K, 2=V
        const int nb = n0 & 1023;           // column base within the target
        #pragma unroll
        for (int mi = 0; mi < 2; mi++) {
            #pragma unroll
            for (int nt = 0; nt < 8; nt++) {
                const int r0 = m0 + wm * 32 + mi * 16 + (lane >> 2);
                const int c0 = nb + wn * 64 + nt * 8 + 2 * (lane & 3);
                if (w == 0) {
                    const long off = blk_off(r0, c0, Dm);
                    *(uint32_t*)(g_Qh + off)     = pack2(acc[mi][nt][0], acc[mi][nt][1]);
                    *(uint32_t*)(g_Qh + off + 4) = pack2(acc[mi][nt][2], acc[mi][nt][3]);
                } else if (w == 1) {
                    const long off = blk_off(r0, c0, Dm);
                    *(uint32_t*)(g_Kh + off)     = pack2(acc[mi][nt][0], acc[mi][nt][1]);
                    *(uint32_t*)(g_Kh + off + 4) = pack2(acc[mi][nt][2], acc[mi][nt][3]);
                } else {
                    const int b   = r0 >> 11;
                    const int rb0 = r0 & 2047;
                    __half* Vb = g_Vt + (long)b * Sq * Dm;
                    Vb[blk_off(c0,     rb0,     Sq)] = __float2half_rn(acc[mi][nt][0]);
                    Vb[blk_off(c0 + 1, rb0,     Sq)] = __float2half_rn(acc[mi][nt][1]);
                    Vb[blk_off(c0,     rb0 + 8, Sq)] = __float2half_rn(acc[mi][nt][2]);
                    Vb[blk_off(c0 + 1, rb0 + 8, Sq)] = __float2half_rn(acc[mi][nt][3]);
                }
            }
        }
    } else if (EPI == 5) {
        // scores: causal mask, E = exp(s/32) (fp32), blocked store, row sums
        __half* Eb = g_Ph + (long)blockIdx.z * Sq * Sq;
        const int lg = lane >> 2, q = lane & 3;
        float rs[2][2] = {{0.f, 0.f}, {0.f, 0.f}};
        #pragma unroll
        for (int mi = 0; mi < 2; mi++) {
            const int ra = m0 + wm * 32 + mi * 16 + lg;
            #pragma unroll
            for (int nt = 0; nt < 8; nt++) {
                const int c0 = n0 + wn * 64 + nt * 8 + 2 * q;
                const float e00 = (c0     <= ra    ) ? __expf(acc[mi][nt][0] * 0.03125f) : 0.f;
                const float e01 = (c0 + 1 <= ra    ) ? __expf(acc[mi][nt][1] * 0.03125f) : 0.f;
                const float e10 = (c0     <= ra + 8) ? __expf(acc[mi][nt][2] * 0.03125f) : 0.f;
                const float e11 = (c0 + 1 <= ra + 8) ? __expf(acc[mi][nt][3] * 0.03125f) : 0.f;
                *(uint32_t*)(Eb + blk_off(ra,     c0, Sq)) = pack2(e00, e01);
                *(uint32_t*)(Eb + blk_off(ra + 8, c0, Sq)) = pack2(e10, e11);
                rs[mi][0] += e00 + e01;
                rs[mi][1] += e10 + e11;
            }
        }
        #pragma unroll
        for (int mi = 0; mi < 2; mi++)
            #pragma unroll
            for (int hi = 0; hi < 2; hi++) {
                rs[mi][hi] += __shfl_xor_sync(0xFFFFFFFFu, rs[mi][hi], 1);
                rs[mi][hi] += __shfl_xor_sync(0xFFFFFFFFu, rs[mi][hi], 2);
            }
        __syncthreads();                     // mainloop smem reads all done
        float* ps = (float*)smd;             // reuse stage-0 smem
        if (q == 0) {
            #pragma unroll
            for (int mi = 0; mi < 2; mi++)
                #pragma unroll
                for (int hi = 0; hi < 2; hi++)
                    ps[(wm * 32 + mi * 16 + hi * 8 + lg) * 2 + wn] = rs[mi][hi];
        }
        __syncthreads();
        if (tid < 64)
            g_Psum[((long)blockIdx.z * Sq + m0 + tid) * 16 + (n0 >> 7)] =
                ps[tid * 2] + ps[tid * 2 + 1];
    } else {
        // EPI == 6: PV output, scaled by per-row inverse sum
        float* Cf = (float*)Cout + (long)blockIdx.z * sC;
        const float* Iv = g_Inv + (long)blockIdx.z * Sq;
        #pragma unroll
        for (int mi = 0; mi < 2; mi++) {
            const int r0 = m0 + wm * 32 + mi * 16 + (lane >> 2);
            const float i0 = Iv[r0], i1 = Iv[r0 + 8];
            #pragma unroll
            for (int nt = 0; nt < 8; nt++) {
                const int c0 = n0 + wn * 64 + nt * 8 + 2 * (lane & 3);
                *(float2*)&Cf[(long)r0 * ldc + c0] =
                    make_float2(acc[mi][nt][0] * i0, acc[mi][nt][1] * i0);
                *(float2*)&Cf[(long)(r0 + 8) * ldc + c0] =
                    make_float2(acc[mi][nt][2] * i1, acc[mi][nt][3] * i1);
            }
        }
    }
}

// ---------------------------------------------------------------------------
extern "C" void kernel_launch(void* const* d_in, const int* in_sizes, int n_in,
                              void* d_out, int out_size)
{
    const float* x  = (const float*)d_in[0];
    const float* Wq = (const float*)d_in[1];
    const float* Wk = (const float*)d_in[2];
    const float* Wv = (const float*)d_in[3];
    float* out = (float*)d_out;

    __half *Xh, *Wcat, *Qh, *Kh, *Vt, *Ph;
    cudaGetSymbolAddress((void**)&Xh,   g_Xh);
    cudaGetSymbolAddress((void**)&Wcat, g_Wcat);
    cudaGetSymbolAddress((void**)&Qh,   g_Qh);
    cudaGetSymbolAddress((void**)&Kh,   g_Kh);
    cudaGetSymbolAddress((void**)&Vt,   g_Vt);
    cudaGetSymbolAddress((void**)&Ph,   g_Ph);

    const int SMEM = 3 * 1536 * 16;   // 73728 B dynamic smem
    cudaFuncSetAttribute((const void*)hgemm<false, false, false, 3>,
        cudaFuncAttributeMaxDynamicSharedMemorySize, SMEM);
    cudaFuncSetAttribute((const void*)hgemm<true, false, true, 5>,
        cudaFuncAttributeMaxDynamicSharedMemorySize, SMEM);
    cudaFuncSetAttribute((const void*)hgemm<false, true, true, 6>,
        cudaFuncAttributeMaxDynamicSharedMemorySize, SMEM);
    cudaFuncSetAttribute((const void*)hgemm<false, false, false, 3>,
        cudaFuncAttributePreferredSharedMemoryCarveout, 100);
    cudaFuncSetAttribute((const void*)hgemm<true, false, true, 5>,
        cudaFuncAttributePreferredSharedMemoryCarveout, 100);
    cudaFuncSetAttribute((const void*)hgemm<false, true, true, 6>,
        cudaFuncAttributePreferredSharedMemoryCarveout, 100);

    const int M = Bsz * Sq;   // 8192

    // 0) pack x; pack all three W^T in ONE launch
    {
        const long nth = (long)M * Dm / 16;
        pack_rm<<<(int)((nth + 255) / 256), 256>>>(x, Xh, Dm, nth);
        dim3 tb(32, 8);
        dim3 gw(Dm / 32, Dm / 32, 3);
        pack_t3<<<gw, tb>>>(Wq, Wk, Wv, Wcat);
    }

    // 1) Fused QKV projection: one launch, epilogue routes Q/K/Vt
    {
        dim3 grid((3 * Dm) / 128, M / 64, 1);
        hgemm<false, false, false, 3><<<grid, 128, SMEM>>>(
            Xh, Wcat, nullptr, Dm, Dm, 0, 0, 0);
    }

    // 2) Scores + mask + exp + partial row sums (causal-skip, heavy first)
    {
        dim3 grid(Sq / 128, Sq / 64, Bsz);
        hgemm<true, false, true, 5><<<grid, 128, SMEM>>>(
            Qh, Kh, nullptr, Dm, Sq,
            (long)Sq * Dm, (long)Sq * Dm, 0);
    }

    // 3) Row-sum finisher -> Inv
    rowsum_k<<<(Bsz * Sq) / 256, 256>>>();

    // 4) O = (E Vt^T) * Inv (causal K-limit, heavy rows first), fp32 out
    {
        dim3 grid(Dm / 128, Sq / 64, Bsz);
        hgemm<false, true, true, 6><<<grid, 128, SMEM>>>(
            Ph, Vt, out, Sq, Dm,
            (long)Sq * Sq, (long)Sq * Dm, (long)Sq * Dm);
    }

    (void)in_sizes; (void)n_in; (void)out_size;
}